// round 11
// baseline (speedup 1.0000x reference)
#include <cuda_runtime.h>

// ---------------------------------------------------------------------------
// GIN layer:  agg = segment_max(feats[src], dst) (empty -> 0)
//             h   = feats + agg
//             h1  = relu(BN(h @ W1 + b1))
//             h2  = relu(BN(h1 @ W2 + b2))
//             out = BN(h2)
// R11: scalar FFMA mainloop (f32x2 reverted — regressed), fused ticket
//      finalize kept; compile-time-bounded combine loops for MLP.
// ---------------------------------------------------------------------------

#define N_NODES 50000
#define N_EDGES 800000
#define D 128
#define CAP 128
#define BN_EPS 1e-5f
#define NBLK_GEMM 391          // ceil(50000 / 128)
#define NBLK_RED 128           // colreduce blocks (391 rows each)

// ----------------------------- scratch (static, no allocs) -----------------
__device__ int   d_cnt[N_NODES];                 // zero-init; re-zeroed each run
__device__ int   d_bucket[N_NODES * CAP];
__device__ float d_H [N_NODES * D];
__device__ float d_Y1[N_NODES * D];
__device__ float d_Y2[N_NODES * D];
__device__ float d_psum[NBLK_GEMM * D];
__device__ float d_psq [NBLK_GEMM * D];
__device__ int   d_ticket[4];                    // per-kernel arrival counters
__device__ float d_scale1[D], d_shift1[D];
__device__ float d_scale2[D], d_shift2[D];
__device__ float d_scale3[D], d_shift3[D];

// ----------------------------- K1: scatter edges into dst buckets ----------
__global__ void scatter_kernel(const int* __restrict__ src,
                               const int* __restrict__ dst) {
    int e = blockIdx.x * blockDim.x + threadIdx.x;
    if (e >= N_EDGES) return;
    int dn = dst[e], sn = src[e];
    int p = atomicAdd(&d_cnt[dn], 1);
    if (p < CAP) d_bucket[dn * CAP + p] = sn;
    // overflow: aggregate_kernel rescans all edges for that node
}

// ----------------------------- K2: warp-per-node max aggregation -----------
__global__ void aggregate_kernel(const float* __restrict__ feats,
                                 const int* __restrict__ src,
                                 const int* __restrict__ dst) {
    int gtid = blockIdx.x * blockDim.x + threadIdx.x;
    int node = gtid >> 5;
    int lane = gtid & 31;
    if (node >= N_NODES) return;
    const float4* f4 = reinterpret_cast<const float4*>(feats);

    int c = d_cnt[node];
    float4 acc = make_float4(-3.402823466e38f, -3.402823466e38f,
                             -3.402823466e38f, -3.402823466e38f);
    if (c <= CAP) {
        const int* bk = d_bucket + node * CAP;
        int e = 0;
        for (; e + 4 <= c; e += 4) {
            int s0 = bk[e+0], s1 = bk[e+1], s2 = bk[e+2], s3 = bk[e+3];
            float4 v0 = f4[s0 * 32 + lane];
            float4 v1 = f4[s1 * 32 + lane];
            float4 v2 = f4[s2 * 32 + lane];
            float4 v3 = f4[s3 * 32 + lane];
            acc.x = fmaxf(acc.x, fmaxf(fmaxf(v0.x, v1.x), fmaxf(v2.x, v3.x)));
            acc.y = fmaxf(acc.y, fmaxf(fmaxf(v0.y, v1.y), fmaxf(v2.y, v3.y)));
            acc.z = fmaxf(acc.z, fmaxf(fmaxf(v0.z, v1.z), fmaxf(v2.z, v3.z)));
            acc.w = fmaxf(acc.w, fmaxf(fmaxf(v0.w, v1.w), fmaxf(v2.w, v3.w)));
        }
        for (; e < c; ++e) {
            int s = bk[e];
            float4 v = f4[s * 32 + lane];
            acc.x = fmaxf(acc.x, v.x); acc.y = fmaxf(acc.y, v.y);
            acc.z = fmaxf(acc.z, v.z); acc.w = fmaxf(acc.w, v.w);
        }
    } else {
        for (int e = 0; e < N_EDGES; ++e) {      // never-path, deterministic
            if (dst[e] == node) {
                float4 v = f4[src[e] * 32 + lane];
                acc.x = fmaxf(acc.x, v.x); acc.y = fmaxf(acc.y, v.y);
                acc.z = fmaxf(acc.z, v.z); acc.w = fmaxf(acc.w, v.w);
            }
        }
    }
    float4 b = f4[node * 32 + lane];
    float4 h;
    if (c == 0) h = b;
    else { h.x = b.x + acc.x; h.y = b.y + acc.y;
           h.z = b.z + acc.z; h.w = b.w + acc.w; }
    reinterpret_cast<float4*>(d_H)[node * 32 + lane] = h;
}

// ------------- fp32 SGEMM + fused BN stats + ticket finalize ---------------
// 512 threads, tile 128(M) x 128(N) x 128(full K), 8x4 scalar microtile.
// Last-arriving block combines partials into scale/shift (fixed order).
__global__ void __launch_bounds__(512)
gemm_kernel(const float* __restrict__ A, const float* __restrict__ Wg,
            const float* __restrict__ bias, float* __restrict__ Y,
            const float* __restrict__ ts, const float* __restrict__ tt,
            const float* __restrict__ g, const float* __restrict__ be,
            float* __restrict__ scale, float* __restrict__ shift,
            int slot) {
    extern __shared__ float smem[];
    float* As = smem;             // [128][128] (m, k)
    float* Ws = smem + 128 * 128; // [128][128] (k, n)
    __shared__ int s_last;

    const int tid  = threadIdx.x;
    const int tcol = tid & 31;    // cols tcol*4 .. +3
    const int trow = tid >> 5;    // rows trow*8 .. +7
    const int block_row = blockIdx.x * 128;

    const float4* A4 = reinterpret_cast<const float4*>(A);
    const float4* W4 = reinterpret_cast<const float4*>(Wg);
    float4*       As4 = reinterpret_cast<float4*>(As);
    float4*       Ws4 = reinterpret_cast<float4*>(Ws);

    #pragma unroll
    for (int i = 0; i < 8; ++i) {
        int f4i = tid + i * 512;              // 0..4095
        int m   = f4i >> 5;
        int k4  = f4i & 31;
        int row = block_row + m;
        float4 v = make_float4(0.f, 0.f, 0.f, 0.f);
        if (row < N_NODES) v = A4[row * 32 + k4];
        if (ts) {
            int k = k4 * 4;
            v.x = fmaxf(fmaf(ts[k+0], v.x, tt[k+0]), 0.f);
            v.y = fmaxf(fmaf(ts[k+1], v.y, tt[k+1]), 0.f);
            v.z = fmaxf(fmaf(ts[k+2], v.z, tt[k+2]), 0.f);
            v.w = fmaxf(fmaf(ts[k+3], v.w, tt[k+3]), 0.f);
        }
        As4[f4i] = v;
        Ws4[f4i] = W4[f4i];
    }
    __syncthreads();

    float acc[8][4];
    #pragma unroll
    for (int i = 0; i < 8; ++i)
        #pragma unroll
        for (int j = 0; j < 4; ++j) acc[i][j] = 0.f;

    #pragma unroll 4
    for (int k = 0; k < 128; ++k) {
        float a[8];
        #pragma unroll
        for (int i = 0; i < 8; ++i) a[i] = As[(trow * 8 + i) * 128 + k];
        float4 bv = Ws4[k * 32 + tcol];
        #pragma unroll
        for (int i = 0; i < 8; ++i) {
            acc[i][0] = fmaf(a[i], bv.x, acc[i][0]);
            acc[i][1] = fmaf(a[i], bv.y, acc[i][1]);
            acc[i][2] = fmaf(a[i], bv.z, acc[i][2]);
            acc[i][3] = fmaf(a[i], bv.w, acc[i][3]);
        }
    }

    float bb[4];
    #pragma unroll
    for (int j = 0; j < 4; ++j) bb[j] = bias[tcol * 4 + j];

    float cs[4] = {0.f, 0.f, 0.f, 0.f};
    float cq[4] = {0.f, 0.f, 0.f, 0.f};

    #pragma unroll
    for (int i = 0; i < 8; ++i) {
        int row = block_row + trow * 8 + i;
        if (row < N_NODES) {
            float v[4];
            #pragma unroll
            for (int j = 0; j < 4; ++j) {
                v[j] = acc[i][j] + bb[j];
                cs[j] += v[j];
                cq[j] += v[j] * v[j];
            }
            *reinterpret_cast<float4*>(Y + row * 128 + tcol * 4) =
                make_float4(v[0], v[1], v[2], v[3]);
        }
    }

    // deterministic per-block column-stat reduction (reuse smem)
    __syncthreads();
    float* ssum = smem;            // [16][128]
    float* ssq  = smem + 2048;     // [16][128]
    #pragma unroll
    for (int j = 0; j < 4; ++j) {
        ssum[trow * 128 + tcol * 4 + j] = cs[j];
        ssq [trow * 128 + tcol * 4 + j] = cq[j];
    }
    __syncthreads();
    if (tid < 128) {
        float s = 0.f, q = 0.f;
        #pragma unroll
        for (int t = 0; t < 16; ++t) {
            s += ssum[t * 128 + tid];
            q += ssq [t * 128 + tid];
        }
        d_psum[blockIdx.x * 128 + tid] = s;
        d_psq [blockIdx.x * 128 + tid] = q;
    }

    // ---- last-block finalize (ticket) ----
    __threadfence();
    __syncthreads();
    if (tid == 0) {
        int old = atomicAdd(&d_ticket[slot], 1);
        s_last = (old == NBLK_GEMM - 1);
        if (s_last) d_ticket[slot] = 0;           // reset for next replay
    }
    __syncthreads();
    if (s_last) {
        __threadfence();
        int c  = tid & 127;
        int sl = tid >> 7;                        // 0..3
        float sm = 0.f, q = 0.f;
        #pragma unroll 8
        for (int b = sl; b < NBLK_GEMM; b += 4) { // fixed-order slices, MLP
            sm += d_psum[b * 128 + c];
            q  += d_psq [b * 128 + c];
        }
        __syncthreads();                          // smem reuse barrier
        ssum[sl * 128 + c] = sm;
        ssq [sl * 128 + c] = q;
        __syncthreads();
        if (sl == 0) {
            float S = 0.f, Q = 0.f;
            #pragma unroll
            for (int t = 0; t < 4; ++t) {         // fixed order
                S += ssum[t * 128 + c];
                Q += ssq [t * 128 + c];
            }
            float m = S / (float)N_NODES;
            float v = Q / (float)N_NODES - m * m;
            float a = g[c] * rsqrtf(v + BN_EPS);
            scale[c] = a;
            shift[c] = be[c] - m * a;
        }
    }
}

// -------------- colreduce (phase-3 stats) + fused finalize -----------------
// 128 blocks x 256 thr: two row-slices per column, then last-block combine.
__global__ void __launch_bounds__(256)
colreduce_kernel(const float* __restrict__ X,
                 const float* __restrict__ ts, const float* __restrict__ tt,
                 const float* __restrict__ g, const float* __restrict__ be,
                 float* __restrict__ scale, float* __restrict__ shift) {
    __shared__ float s0[128], q0[128];
    __shared__ int s_last;
    const int t  = threadIdx.x;
    const int c  = t & 127;
    const int sl = t >> 7;                        // 0 or 1
    int r0 = blockIdx.x * 391;
    int r1 = r0 + 391; if (r1 > N_NODES) r1 = N_NODES;
    float sc = ts[c], sh = tt[c];
    float sm = 0.f, sq = 0.f;
    for (int r = r0 + sl; r < r1; r += 2) {       // fixed order per slice
        float v = fmaxf(fmaf(sc, X[r * 128 + c], sh), 0.f);
        sm += v; sq += v * v;
    }
    if (sl == 1) { s0[c] = sm; q0[c] = sq; }
    __syncthreads();
    if (sl == 0) {                                // fixed combine order
        sm += s0[c]; sq += q0[c];
        d_psum[blockIdx.x * 128 + c] = sm;
        d_psq [blockIdx.x * 128 + c] = sq;
    }
    __threadfence();
    __syncthreads();
    if (t == 0) {
        int old = atomicAdd(&d_ticket[2], 1);
        s_last = (old == NBLK_RED - 1);
        if (s_last) d_ticket[2] = 0;
    }
    __syncthreads();
    if (s_last) {
        __threadfence();
        float sm2 = 0.f, q2 = 0.f;
        #pragma unroll 8
        for (int b = sl; b < NBLK_RED; b += 2) {  // fixed order, MLP
            sm2 += d_psum[b * 128 + c];
            q2  += d_psq [b * 128 + c];
        }
        __syncthreads();
        if (sl == 1) { s0[c] = sm2; q0[c] = q2; }
        __syncthreads();
        if (sl == 0) {
            float S = sm2 + s0[c];
            float Q = q2  + q0[c];
            float m = S / (float)N_NODES;
            float v = Q / (float)N_NODES - m * m;
            float a = g[c] * rsqrtf(v + BN_EPS);
            scale[c] = a;
            shift[c] = be[c] - m * a;
        }
    }
}

// ----------------------------- final elementwise (float4) ------------------
__global__ void final_kernel(float4* __restrict__ out4) {
    int i = blockIdx.x * blockDim.x + threadIdx.x;   // 0 .. 1.6M-1
    if (i >= N_NODES * 32) return;
    if (i < N_NODES) d_cnt[i] = 0;                   // prep next graph replay
    int c = (i & 31) * 4;
    float4 v = reinterpret_cast<const float4*>(d_Y2)[i];
    float4 o;
    o.x = fmaf(d_scale3[c+0], fmaxf(fmaf(d_scale2[c+0], v.x, d_shift2[c+0]), 0.f), d_shift3[c+0]);
    o.y = fmaf(d_scale3[c+1], fmaxf(fmaf(d_scale2[c+1], v.y, d_shift2[c+1]), 0.f), d_shift3[c+1]);
    o.z = fmaf(d_scale3[c+2], fmaxf(fmaf(d_scale2[c+2], v.z, d_shift2[c+2]), 0.f), d_shift3[c+2]);
    o.w = fmaf(d_scale3[c+3], fmaxf(fmaf(d_scale2[c+3], v.w, d_shift2[c+3]), 0.f), d_shift3[c+3]);
    out4[i] = o;
}

// ---------------------------------------------------------------------------
extern "C" void kernel_launch(void* const* d_in, const int* in_sizes, int n_in,
                              void* d_out, int out_size) {
    const float* feats = (const float*)d_in[0];
    const int*   src   = (const int*)  d_in[1];
    const int*   dst   = (const int*)  d_in[2];
    const float* W1    = (const float*)d_in[3];
    const float* b1    = (const float*)d_in[4];
    const float* g1    = (const float*)d_in[5];
    const float* be1   = (const float*)d_in[6];
    const float* W2    = (const float*)d_in[7];
    const float* b2    = (const float*)d_in[8];
    const float* g2    = (const float*)d_in[9];
    const float* be2   = (const float*)d_in[10];
    const float* g3    = (const float*)d_in[11];
    const float* be3   = (const float*)d_in[12];
    float* out = (float*)d_out;

    static bool attr_set = false;
    const int GEMM_SMEM = 2 * 128 * 128 * sizeof(float);  // 128 KB
    if (!attr_set) {
        cudaFuncSetAttribute(gemm_kernel,
                             cudaFuncAttributeMaxDynamicSharedMemorySize,
                             GEMM_SMEM);
        attr_set = true;
    }

    float *s1, *t1, *s2, *t2, *s3, *t3;
    cudaGetSymbolAddress((void**)&s1, d_scale1);
    cudaGetSymbolAddress((void**)&t1, d_shift1);
    cudaGetSymbolAddress((void**)&s2, d_scale2);
    cudaGetSymbolAddress((void**)&t2, d_shift2);
    cudaGetSymbolAddress((void**)&s3, d_scale3);
    cudaGetSymbolAddress((void**)&t3, d_shift3);
    float *H, *Y1, *Y2;
    cudaGetSymbolAddress((void**)&H,  d_H);
    cudaGetSymbolAddress((void**)&Y1, d_Y1);
    cudaGetSymbolAddress((void**)&Y2, d_Y2);

    scatter_kernel<<<(N_EDGES + 255) / 256, 256>>>(src, dst);
    aggregate_kernel<<<(N_NODES * 32 + 255) / 256, 256>>>(feats, src, dst);

    // Y1 = H @ W1 + b1   (+ fused stats + finalize -> scale1/shift1)
    gemm_kernel<<<NBLK_GEMM, 512, GEMM_SMEM>>>(H, W1, b1, Y1,
                                               nullptr, nullptr,
                                               g1, be1, s1, t1, 0);
    // Y2 = relu(BN(Y1)) @ W2 + b2  (+ fused stats + finalize -> scale2/shift2)
    gemm_kernel<<<NBLK_GEMM, 512, GEMM_SMEM>>>(Y1, W2, b2, Y2,
                                               s1, t1,
                                               g2, be2, s2, t2, 1);
    // stats of h2 = relu(BN(Y2))  (+ fused finalize -> scale3/shift3)
    colreduce_kernel<<<NBLK_RED, 256>>>(Y2, s2, t2, g3, be3, s3, t3);
    // out = BN3(relu(BN2(Y2)))  (+ re-zero d_cnt)
    final_kernel<<<(N_NODES * 32 + 255) / 256, 256>>>(
        reinterpret_cast<float4*>(out));
}

// round 14
// speedup vs baseline: 1.4870x; 1.4870x over previous
#include <cuda_runtime.h>
#include <cuda_bf16.h>

// ---------------------------------------------------------------------------
// GIN layer:  agg = segment_max(feats[src], dst) (empty -> 0)
//             h   = feats + agg
//             h1  = relu(BN(h @ W1 + b1))
//             h2  = relu(BN(h1 @ W2 + b2))
//             out = BN(h2)
// R14: mma.sync bf16 split-precision GEMM (tcgen05 is sm_103a-only PTX and
//      the harness emits compute_103 PTX -> use HMMA mma.sync instead).
//      D = Ahi*Whi + Ahi*Wlo + Alo*Whi, fp32 accum. R9 skeleton elsewhere.
// ---------------------------------------------------------------------------

#define N_NODES 50000
#define N_EDGES 800000
#define D 128
#define CAP 128
#define BN_EPS 1e-5f
#define NBLK_GEMM 391          // ceil(50000 / 128)
#define NBLK_RED 500           // colreduce blocks (100 rows each)
#define NBLK_MAX 500

typedef unsigned long long ull;

// ----------------------------- scratch (static, no allocs) -----------------
__device__ int   d_cnt[N_NODES];                 // zero-init; re-zeroed each run
__device__ int   d_bucket[N_NODES * CAP];
__device__ float d_H [N_NODES * D];
__device__ float d_Y1[N_NODES * D];
__device__ float d_Y2[N_NODES * D];
__device__ float d_psum[NBLK_MAX * D];
__device__ float d_psq [NBLK_MAX * D];
__device__ float d_scale1[D], d_shift1[D];
__device__ float d_scale2[D], d_shift2[D];
__device__ float d_scale3[D], d_shift3[D];
// pre-split bf16 weight images, [n][k] row-major, XOR-swizzled
__device__ __nv_bfloat16 d_W1hi[D * D], d_W1lo[D * D];
__device__ __nv_bfloat16 d_W2hi[D * D], d_W2lo[D * D];

// XOR swizzle on a [row][128] bf16 row-major tile (256B rows):
// phys_byte = row*256 + (col_byte ^ ((row&7)<<4))  -> conflict-free ldmatrix
__device__ __forceinline__ int swz(int row, int col_byte) {
    return row * 256 + (col_byte ^ ((row & 7) << 4));
}

__device__ __forceinline__ unsigned smem_u32(const void* p) {
    unsigned a;
    asm("{ .reg .u64 t; cvta.to.shared.u64 t, %1; cvt.u32.u64 %0, t; }"
        : "=r"(a) : "l"(p));
    return a;
}

#define LDSM_X4(r0, r1, r2, r3, addr) \
    asm volatile("ldmatrix.sync.aligned.m8n8.x4.shared.b16 {%0,%1,%2,%3}, [%4];" \
                 : "=r"(r0), "=r"(r1), "=r"(r2), "=r"(r3) : "r"(addr))

#define MMA_BF16(c0, c1, c2, c3, a0, a1, a2, a3, b0, b1) \
    asm volatile("mma.sync.aligned.m16n8k16.row.col.f32.bf16.bf16.f32 " \
                 "{%0,%1,%2,%3}, {%4,%5,%6,%7}, {%8,%9}, {%0,%1,%2,%3};" \
                 : "+f"(c0), "+f"(c1), "+f"(c2), "+f"(c3) \
                 : "r"(a0), "r"(a1), "r"(a2), "r"(a3), "r"(b0), "r"(b1))

// ----------------------------- K1: scatter ---------------------------------
__global__ void scatter_kernel(const int* __restrict__ src,
                               const int* __restrict__ dst) {
    int e = blockIdx.x * blockDim.x + threadIdx.x;
    if (e >= N_EDGES) return;
    int dn = dst[e], sn = src[e];
    int p = atomicAdd(&d_cnt[dn], 1);
    if (p < CAP) d_bucket[dn * CAP + p] = sn;
}

// ----------------------------- K2: warp-per-node max -----------------------
__global__ void aggregate_kernel(const float* __restrict__ feats,
                                 const int* __restrict__ src,
                                 const int* __restrict__ dst) {
    int gtid = blockIdx.x * blockDim.x + threadIdx.x;
    int node = gtid >> 5;
    int lane = gtid & 31;
    if (node >= N_NODES) return;
    const float4* f4 = reinterpret_cast<const float4*>(feats);

    int c = d_cnt[node];
    float4 acc = make_float4(-3.402823466e38f, -3.402823466e38f,
                             -3.402823466e38f, -3.402823466e38f);
    if (c <= CAP) {
        const int* bk = d_bucket + node * CAP;
        int e = 0;
        for (; e + 4 <= c; e += 4) {
            int s0 = bk[e+0], s1 = bk[e+1], s2 = bk[e+2], s3 = bk[e+3];
            float4 v0 = f4[s0 * 32 + lane];
            float4 v1 = f4[s1 * 32 + lane];
            float4 v2 = f4[s2 * 32 + lane];
            float4 v3 = f4[s3 * 32 + lane];
            acc.x = fmaxf(acc.x, fmaxf(fmaxf(v0.x, v1.x), fmaxf(v2.x, v3.x)));
            acc.y = fmaxf(acc.y, fmaxf(fmaxf(v0.y, v1.y), fmaxf(v2.y, v3.y)));
            acc.z = fmaxf(acc.z, fmaxf(fmaxf(v0.z, v1.z), fmaxf(v2.z, v3.z)));
            acc.w = fmaxf(acc.w, fmaxf(fmaxf(v0.w, v1.w), fmaxf(v2.w, v3.w)));
        }
        for (; e < c; ++e) {
            int s = bk[e];
            float4 v = f4[s * 32 + lane];
            acc.x = fmaxf(acc.x, v.x); acc.y = fmaxf(acc.y, v.y);
            acc.z = fmaxf(acc.z, v.z); acc.w = fmaxf(acc.w, v.w);
        }
    } else {
        for (int e = 0; e < N_EDGES; ++e) {      // never-path, deterministic
            if (dst[e] == node) {
                float4 v = f4[src[e] * 32 + lane];
                acc.x = fmaxf(acc.x, v.x); acc.y = fmaxf(acc.y, v.y);
                acc.z = fmaxf(acc.z, v.z); acc.w = fmaxf(acc.w, v.w);
            }
        }
    }
    float4 b = f4[node * 32 + lane];
    float4 h;
    if (c == 0) h = b;
    else { h.x = b.x + acc.x; h.y = b.y + acc.y;
           h.z = b.z + acc.z; h.w = b.w + acc.w; }
    reinterpret_cast<float4*>(d_H)[node * 32 + lane] = h;
}

// ------------------ prep: split W -> bf16 hi/lo, [n][k] swizzled -----------
__global__ void prep_kernel(const float* __restrict__ W1,
                            const float* __restrict__ W2) {
    int idx = blockIdx.x * blockDim.x + threadIdx.x;   // 0..32767
    if (idx >= 2 * D * D) return;
    int which = idx >> 14;
    int e = idx & (D * D - 1);
    int k = e >> 7, n = e & 127;                       // consecutive n: coalesced
    const float* W = which ? W2 : W1;
    float x = W[k * D + n];                            // W[k][n]
    __nv_bfloat16 h = __float2bfloat16(x);
    __nv_bfloat16 l = __float2bfloat16(x - __bfloat162float(h));
    int off = swz(n, k * 2) >> 1;                      // B image: row=n, col=k
    if (which) { d_W2hi[off] = h; d_W2lo[off] = l; }
    else       { d_W1hi[off] = h; d_W1lo[off] = l; }
}

// -------------- mma.sync bf16-split GEMM + fused BN column stats -----------
// 256 threads = 8 warps (2x4). Warp tile m64 x n32. Full K=128 in smem.
#define SM_AHI 0
#define SM_ALO 32768
#define SM_BHI 65536
#define SM_BLO 98304
#define GEMM_SMEM 131072
#define SM_YT   0              // epilogue reuse (A regions dead)
#define SM_PS   98304          // stat partials (B regions dead)
#define YT_PITCH 132

__global__ void __launch_bounds__(256)
gemm_kernel(const float* __restrict__ A,
            const __nv_bfloat16* __restrict__ Whi,
            const __nv_bfloat16* __restrict__ Wlo,
            const float* __restrict__ bias, float* __restrict__ Y,
            const float* __restrict__ ts, const float* __restrict__ tt) {
    extern __shared__ char smem[];
    const int tid  = threadIdx.x;
    const int wid  = tid >> 5;
    const int lane = tid & 31;
    const int block_row = blockIdx.x * 128;
    const unsigned smem_b = smem_u32(smem);

    const int warp_m = (wid >> 2) * 64;    // 0 or 64
    const int warp_n = (wid & 3) * 32;     // 0,32,64,96

    // ---- A tile: fp32 -> bf16 hi/lo, swizzled row-major [m][k] ----
    const float4* A4 = reinterpret_cast<const float4*>(A);
    #pragma unroll
    for (int i = 0; i < 16; ++i) {
        int f4i = tid + i * 256;             // 0..4095
        int m   = f4i >> 5;
        int k4  = f4i & 31;
        int row = block_row + m;
        float4 v = make_float4(0.f, 0.f, 0.f, 0.f);
        if (row < N_NODES) v = A4[row * 32 + k4];
        if (ts) {
            int k = k4 * 4;
            v.x = fmaxf(fmaf(ts[k+0], v.x, tt[k+0]), 0.f);
            v.y = fmaxf(fmaf(ts[k+1], v.y, tt[k+1]), 0.f);
            v.z = fmaxf(fmaf(ts[k+2], v.z, tt[k+2]), 0.f);
            v.w = fmaxf(fmaf(ts[k+3], v.w, tt[k+3]), 0.f);
        }
        __nv_bfloat162 h01 = __floats2bfloat162_rn(v.x, v.y);
        __nv_bfloat162 h23 = __floats2bfloat162_rn(v.z, v.w);
        float2 hf01 = __bfloat1622float2(h01);
        float2 hf23 = __bfloat1622float2(h23);
        __nv_bfloat162 l01 = __floats2bfloat162_rn(v.x - hf01.x, v.y - hf01.y);
        __nv_bfloat162 l23 = __floats2bfloat162_rn(v.z - hf23.x, v.w - hf23.y);
        int off = swz(m, k4 * 8);            // 8B chunk, 8-aligned, swizzle-safe
        ull hp = ((ull)*(unsigned*)&h23 << 32) | *(unsigned*)&h01;
        ull lp = ((ull)*(unsigned*)&l23 << 32) | *(unsigned*)&l01;
        *reinterpret_cast<ull*>(smem + SM_AHI + off) = hp;
        *reinterpret_cast<ull*>(smem + SM_ALO + off) = lp;
    }

    // ---- W images: straight 32KB copies (already split+transposed+swizzled)
    {
        const uint4* sh = reinterpret_cast<const uint4*>(Whi);
        const uint4* sl = reinterpret_cast<const uint4*>(Wlo);
        uint4* dh = reinterpret_cast<uint4*>(smem + SM_BHI);
        uint4* dl = reinterpret_cast<uint4*>(smem + SM_BLO);
        #pragma unroll
        for (int i = 0; i < 8; ++i) {
            dh[tid + i * 256] = sh[tid + i * 256];
            dl[tid + i * 256] = sl[tid + i * 256];
        }
    }
    __syncthreads();

    // ---- mainloop: 8 K-steps of 16; 3 split terms accumulated in fp32 ----
    float c[4][4][4];
    #pragma unroll
    for (int mt = 0; mt < 4; ++mt)
        #pragma unroll
        for (int nt = 0; nt < 4; ++nt)
            #pragma unroll
            for (int q = 0; q < 4; ++q) c[mt][nt][q] = 0.f;

    const int a_row  = lane & 15;            // + warp_m + mt*16
    const int a_koff = (lane >> 4) * 8;      // k element offset
    const int b_nrow = (lane & 7) + ((lane >> 4) & 1) * 8;  // + warp_n + p*16
    const int b_koff = ((lane >> 3) & 1) * 8;

    #pragma unroll
    for (int ks = 0; ks < 8; ++ks) {
        int kb = ks * 16;
        // B fragments: hi and lo, 4 n-tiles each (2x ldmatrix.x4 per image)
        unsigned bh[8], bl[8];
        #pragma unroll
        for (int p = 0; p < 2; ++p) {
            int n = warp_n + p * 16 + b_nrow;
            int boff = swz(n, (kb + b_koff) * 2);
            LDSM_X4(bh[p*4+0], bh[p*4+1], bh[p*4+2], bh[p*4+3],
                    smem_b + SM_BHI + boff);
            LDSM_X4(bl[p*4+0], bl[p*4+1], bl[p*4+2], bl[p*4+3],
                    smem_b + SM_BLO + boff);
        }
        #pragma unroll
        for (int mt = 0; mt < 4; ++mt) {
            int m = warp_m + mt * 16 + a_row;
            int aoff = swz(m, (kb + a_koff) * 2);
            unsigned ah0, ah1, ah2, ah3, al0, al1, al2, al3;
            LDSM_X4(ah0, ah1, ah2, ah3, smem_b + SM_AHI + aoff);
            LDSM_X4(al0, al1, al2, al3, smem_b + SM_ALO + aoff);
            #pragma unroll
            for (int nt = 0; nt < 4; ++nt) {
                unsigned b0h = bh[(nt >> 1) * 4 + (nt & 1) * 2];
                unsigned b1h = bh[(nt >> 1) * 4 + (nt & 1) * 2 + 1];
                unsigned b0l = bl[(nt >> 1) * 4 + (nt & 1) * 2];
                unsigned b1l = bl[(nt >> 1) * 4 + (nt & 1) * 2 + 1];
                MMA_BF16(c[mt][nt][0], c[mt][nt][1], c[mt][nt][2], c[mt][nt][3],
                         ah0, ah1, ah2, ah3, b0h, b1h);
                MMA_BF16(c[mt][nt][0], c[mt][nt][1], c[mt][nt][2], c[mt][nt][3],
                         ah0, ah1, ah2, ah3, b0l, b1l);
                MMA_BF16(c[mt][nt][0], c[mt][nt][1], c[mt][nt][2], c[mt][nt][3],
                         al0, al1, al2, al3, b0h, b1h);
            }
        }
    }
    __syncthreads();   // A/B smem dead; reuse as Yt

    // ---- epilogue: fragments (+bias, zero invalid rows) -> smem Yt ----
    float* Yt = reinterpret_cast<float*>(smem + SM_YT);   // [128][YT_PITCH]
    {
        int fr = lane >> 2;                  // 0..7
        int fc = (lane & 3) * 2;
        #pragma unroll
        for (int mt = 0; mt < 4; ++mt) {
            int r0 = warp_m + mt * 16 + fr;
            bool v0 = (block_row + r0)     < N_NODES;
            bool v1 = (block_row + r0 + 8) < N_NODES;
            #pragma unroll
            for (int nt = 0; nt < 4; ++nt) {
                int cc = warp_n + nt * 8 + fc;
                float bb0 = bias[cc], bb1 = bias[cc + 1];
                Yt[r0 * YT_PITCH + cc]           = v0 ? c[mt][nt][0] + bb0 : 0.f;
                Yt[r0 * YT_PITCH + cc + 1]       = v0 ? c[mt][nt][1] + bb1 : 0.f;
                Yt[(r0 + 8) * YT_PITCH + cc]     = v1 ? c[mt][nt][2] + bb0 : 0.f;
                Yt[(r0 + 8) * YT_PITCH + cc + 1] = v1 ? c[mt][nt][3] + bb1 : 0.f;
            }
        }
    }
    __syncthreads();

    // ---- gmem write + deterministic column stats from Yt ----
    {
        float* psm = reinterpret_cast<float*>(smem + SM_PS);          // [8][128]
        float* psq = reinterpret_cast<float*>(smem + SM_PS + 4096);   // [8][128]
        int c4   = tid & 31;                 // cols c4*4 .. +3
        int rseg = tid >> 5;                 // rows rseg*16 .. +15
        float cs[4] = {0.f, 0.f, 0.f, 0.f};
        float cq[4] = {0.f, 0.f, 0.f, 0.f};
        #pragma unroll
        for (int r = 0; r < 16; ++r) {
            int row = rseg * 16 + r;
            float4 v = *reinterpret_cast<float4*>(&Yt[row * YT_PITCH + c4 * 4]);
            cs[0] += v.x; cq[0] += v.x * v.x;
            cs[1] += v.y; cq[1] += v.y * v.y;
            cs[2] += v.z; cq[2] += v.z * v.z;
            cs[3] += v.w; cq[3] += v.w * v.w;
            int grow = block_row + row;
            if (grow < N_NODES)
                *reinterpret_cast<float4*>(Y + grow * 128 + c4 * 4) = v;
        }
        #pragma unroll
        for (int j = 0; j < 4; ++j) {
            psm[rseg * 128 + c4 * 4 + j] = cs[j];
            psq[rseg * 128 + c4 * 4 + j] = cq[j];
        }
        __syncthreads();
        if (tid < 128) {
            float S = 0.f, Q = 0.f;
            #pragma unroll
            for (int t = 0; t < 8; ++t) {    // fixed order -> deterministic
                S += psm[t * 128 + tid];
                Q += psq[t * 128 + tid];
            }
            d_psum[blockIdx.x * 128 + tid] = S;
            d_psq [blockIdx.x * 128 + tid] = Q;
        }
    }
}

// ----------------------------- colreduce (phase-3 stats) -------------------
__global__ void colreduce_kernel(const float* __restrict__ X,
                                 const float* __restrict__ ts,
                                 const float* __restrict__ tt) {
    int c = threadIdx.x;
    int r0 = blockIdx.x * 100;
    int r1 = r0 + 100; if (r1 > N_NODES) r1 = N_NODES;
    float sc = ts[c], sh = tt[c];
    float sm = 0.f, sq = 0.f;
    for (int r = r0; r < r1; ++r) {
        float v = fmaxf(fmaf(sc, X[r * 128 + c], sh), 0.f);
        sm += v; sq += v * v;
    }
    d_psum[blockIdx.x * 128 + c] = sm;
    d_psq [blockIdx.x * 128 + c] = sq;
}

// ----------------------------- parallel finalize (R9, proven) --------------
__global__ void __launch_bounds__(256)
finalize_kernel(const float* __restrict__ g, const float* __restrict__ be,
                float* __restrict__ scale, float* __restrict__ shift,
                int nblk) {
    __shared__ float ss[256];
    __shared__ float sq[256];
    const int c = blockIdx.x;
    const int t = threadIdx.x;
    float sm = 0.f, q = 0.f;
    for (int b = t; b < nblk; b += 256) {
        sm += d_psum[b * 128 + c];
        q  += d_psq [b * 128 + c];
    }
    ss[t] = sm; sq[t] = q;
    __syncthreads();
    #pragma unroll
    for (int s = 128; s > 0; s >>= 1) {
        if (t < s) { ss[t] += ss[t + s]; sq[t] += sq[t + s]; }
        __syncthreads();
    }
    if (t == 0) {
        float m = ss[0] / (float)N_NODES;
        float v = sq[0] / (float)N_NODES - m * m;
        float a = g[c] * rsqrtf(v + BN_EPS);
        scale[c] = a;
        shift[c] = be[c] - m * a;
    }
}

// ----------------------------- final elementwise (float4) ------------------
__global__ void final_kernel(float4* __restrict__ out4) {
    int i = blockIdx.x * blockDim.x + threadIdx.x;
    if (i >= N_NODES * 32) return;
    if (i < N_NODES) d_cnt[i] = 0;               // prep next graph replay
    int c = (i & 31) * 4;
    float4 v = reinterpret_cast<const float4*>(d_Y2)[i];
    float4 o;
    o.x = fmaf(d_scale3[c+0], fmaxf(fmaf(d_scale2[c+0], v.x, d_shift2[c+0]), 0.f), d_shift3[c+0]);
    o.y = fmaf(d_scale3[c+1], fmaxf(fmaf(d_scale2[c+1], v.y, d_shift2[c+1]), 0.f), d_shift3[c+1]);
    o.z = fmaf(d_scale3[c+2], fmaxf(fmaf(d_scale2[c+2], v.z, d_shift2[c+2]), 0.f), d_shift3[c+2]);
    o.w = fmaf(d_scale3[c+3], fmaxf(fmaf(d_scale2[c+3], v.w, d_shift2[c+3]), 0.f), d_shift3[c+3]);
    out4[i] = o;
}

// ---------------------------------------------------------------------------
extern "C" void kernel_launch(void* const* d_in, const int* in_sizes, int n_in,
                              void* d_out, int out_size) {
    const float* feats = (const float*)d_in[0];
    const int*   src   = (const int*)  d_in[1];
    const int*   dst   = (const int*)  d_in[2];
    const float* W1    = (const float*)d_in[3];
    const float* b1    = (const float*)d_in[4];
    const float* g1    = (const float*)d_in[5];
    const float* be1   = (const float*)d_in[6];
    const float* W2    = (const float*)d_in[7];
    const float* b2    = (const float*)d_in[8];
    const float* g2    = (const float*)d_in[9];
    const float* be2   = (const float*)d_in[10];
    const float* g3    = (const float*)d_in[11];
    const float* be3   = (const float*)d_in[12];
    float* out = (float*)d_out;

    static bool attr_set = false;
    if (!attr_set) {
        cudaFuncSetAttribute(gemm_kernel,
                             cudaFuncAttributeMaxDynamicSharedMemorySize,
                             GEMM_SMEM);
        attr_set = true;
    }

    float *s1, *t1, *s2, *t2, *s3, *t3;
    cudaGetSymbolAddress((void**)&s1, d_scale1);
    cudaGetSymbolAddress((void**)&t1, d_shift1);
    cudaGetSymbolAddress((void**)&s2, d_scale2);
    cudaGetSymbolAddress((void**)&t2, d_shift2);
    cudaGetSymbolAddress((void**)&s3, d_scale3);
    cudaGetSymbolAddress((void**)&t3, d_shift3);
    float *H, *Y1, *Y2;
    cudaGetSymbolAddress((void**)&H,  d_H);
    cudaGetSymbolAddress((void**)&Y1, d_Y1);
    cudaGetSymbolAddress((void**)&Y2, d_Y2);
    __nv_bfloat16 *w1h, *w1l, *w2h, *w2l;
    cudaGetSymbolAddress((void**)&w1h, d_W1hi);
    cudaGetSymbolAddress((void**)&w1l, d_W1lo);
    cudaGetSymbolAddress((void**)&w2h, d_W2hi);
    cudaGetSymbolAddress((void**)&w2l, d_W2lo);

    prep_kernel<<<128, 256>>>(W1, W2);
    scatter_kernel<<<(N_EDGES + 255) / 256, 256>>>(src, dst);
    aggregate_kernel<<<(N_NODES * 32 + 255) / 256, 256>>>(feats, src, dst);

    // Y1 = H @ W1 + b1   (+ fused column stats)
    gemm_kernel<<<NBLK_GEMM, 256, GEMM_SMEM>>>(H, w1h, w1l, b1, Y1,
                                               nullptr, nullptr);
    finalize_kernel<<<D, 256>>>(g1, be1, s1, t1, NBLK_GEMM);
    // Y2 = relu(BN(Y1)) @ W2 + b2   (BN+ReLU fused into A load)
    gemm_kernel<<<NBLK_GEMM, 256, GEMM_SMEM>>>(Y1, w2h, w2l, b2, Y2,
                                               s1, t1);
    finalize_kernel<<<D, 256>>>(g2, be2, s2, t2, NBLK_GEMM);
    // stats of h2 = relu(BN(Y2))
    colreduce_kernel<<<NBLK_RED, 128>>>(Y2, s2, t2);
    finalize_kernel<<<D, 256>>>(g3, be3, s3, t3, NBLK_RED);
    // out = BN3(relu(BN2(Y2)))  (+ re-zero d_cnt)
    final_kernel<<<(N_NODES * 32 + 255) / 256, 256>>>(
        reinterpret_cast<float4*>(out));
}

// round 17
// speedup vs baseline: 1.4922x; 1.0035x over previous
#include <cuda_runtime.h>
#include <cuda_bf16.h>

// ---------------------------------------------------------------------------
// GIN layer:  agg = segment_max(feats[src], dst) (empty -> 0)
//             h   = feats + agg
//             h1  = relu(BN(h @ W1 + b1))
//             h2  = relu(BN(h1 @ W2 + b2))
//             out = BN(h2)
// R15: mma.sync bf16 split GEMM at 512 threads (16 warps, m32xn32/warp)
//      + cp.async W-copy overlapped with A convert. R14 otherwise.
// ---------------------------------------------------------------------------

#define N_NODES 50000
#define N_EDGES 800000
#define D 128
#define CAP 128
#define BN_EPS 1e-5f
#define NBLK_GEMM 391          // ceil(50000 / 128)
#define NBLK_RED 500           // colreduce blocks (100 rows each)
#define NBLK_MAX 500

typedef unsigned long long ull;

// ----------------------------- scratch (static, no allocs) -----------------
__device__ int   d_cnt[N_NODES];                 // zero-init; re-zeroed each run
__device__ int   d_bucket[N_NODES * CAP];
__device__ float d_H [N_NODES * D];
__device__ float d_Y1[N_NODES * D];
__device__ float d_Y2[N_NODES * D];
__device__ float d_psum[NBLK_MAX * D];
__device__ float d_psq [NBLK_MAX * D];
__device__ float d_scale1[D], d_shift1[D];
__device__ float d_scale2[D], d_shift2[D];
__device__ float d_scale3[D], d_shift3[D];
// pre-split bf16 weight images, [n][k] row-major, XOR-swizzled
__device__ __nv_bfloat16 d_W1hi[D * D], d_W1lo[D * D];
__device__ __nv_bfloat16 d_W2hi[D * D], d_W2lo[D * D];

// XOR swizzle on a [row][128] bf16 row-major tile (256B rows)
__device__ __forceinline__ int swz(int row, int col_byte) {
    return row * 256 + (col_byte ^ ((row & 7) << 4));
}

__device__ __forceinline__ unsigned smem_u32(const void* p) {
    unsigned a;
    asm("{ .reg .u64 t; cvta.to.shared.u64 t, %1; cvt.u32.u64 %0, t; }"
        : "=r"(a) : "l"(p));
    return a;
}

#define LDSM_X4(r0, r1, r2, r3, addr) \
    asm volatile("ldmatrix.sync.aligned.m8n8.x4.shared.b16 {%0,%1,%2,%3}, [%4];" \
                 : "=r"(r0), "=r"(r1), "=r"(r2), "=r"(r3) : "r"(addr))

#define MMA_BF16(c0, c1, c2, c3, a0, a1, a2, a3, b0, b1) \
    asm volatile("mma.sync.aligned.m16n8k16.row.col.f32.bf16.bf16.f32 " \
                 "{%0,%1,%2,%3}, {%4,%5,%6,%7}, {%8,%9}, {%0,%1,%2,%3};" \
                 : "+f"(c0), "+f"(c1), "+f"(c2), "+f"(c3) \
                 : "r"(a0), "r"(a1), "r"(a2), "r"(a3), "r"(b0), "r"(b1))

#define CP_ASYNC16(sm, gp) \
    asm volatile("cp.async.ca.shared.global [%0], [%1], 16;" \
                 :: "r"(sm), "l"(gp))
#define CP_ASYNC_WAIT_ALL() \
    asm volatile("cp.async.commit_group;\n\tcp.async.wait_group 0;" ::: "memory")

// ----------------------------- K1: scatter ---------------------------------
__global__ void scatter_kernel(const int* __restrict__ src,
                               const int* __restrict__ dst) {
    int e = blockIdx.x * blockDim.x + threadIdx.x;
    if (e >= N_EDGES) return;
    int dn = dst[e], sn = src[e];
    int p = atomicAdd(&d_cnt[dn], 1);
    if (p < CAP) d_bucket[dn * CAP + p] = sn;
}

// ----------------------------- K2: warp-per-node max -----------------------
__global__ void aggregate_kernel(const float* __restrict__ feats,
                                 const int* __restrict__ src,
                                 const int* __restrict__ dst) {
    int gtid = blockIdx.x * blockDim.x + threadIdx.x;
    int node = gtid >> 5;
    int lane = gtid & 31;
    if (node >= N_NODES) return;
    const float4* f4 = reinterpret_cast<const float4*>(feats);

    int c = d_cnt[node];
    float4 acc = make_float4(-3.402823466e38f, -3.402823466e38f,
                             -3.402823466e38f, -3.402823466e38f);
    if (c <= CAP) {
        const int* bk = d_bucket + node * CAP;
        int e = 0;
        for (; e + 4 <= c; e += 4) {
            int s0 = bk[e+0], s1 = bk[e+1], s2 = bk[e+2], s3 = bk[e+3];
            float4 v0 = f4[s0 * 32 + lane];
            float4 v1 = f4[s1 * 32 + lane];
            float4 v2 = f4[s2 * 32 + lane];
            float4 v3 = f4[s3 * 32 + lane];
            acc.x = fmaxf(acc.x, fmaxf(fmaxf(v0.x, v1.x), fmaxf(v2.x, v3.x)));
            acc.y = fmaxf(acc.y, fmaxf(fmaxf(v0.y, v1.y), fmaxf(v2.y, v3.y)));
            acc.z = fmaxf(acc.z, fmaxf(fmaxf(v0.z, v1.z), fmaxf(v2.z, v3.z)));
            acc.w = fmaxf(acc.w, fmaxf(fmaxf(v0.w, v1.w), fmaxf(v2.w, v3.w)));
        }
        for (; e < c; ++e) {
            int s = bk[e];
            float4 v = f4[s * 32 + lane];
            acc.x = fmaxf(acc.x, v.x); acc.y = fmaxf(acc.y, v.y);
            acc.z = fmaxf(acc.z, v.z); acc.w = fmaxf(acc.w, v.w);
        }
    } else {
        for (int e = 0; e < N_EDGES; ++e) {      // never-path, deterministic
            if (dst[e] == node) {
                float4 v = f4[src[e] * 32 + lane];
                acc.x = fmaxf(acc.x, v.x); acc.y = fmaxf(acc.y, v.y);
                acc.z = fmaxf(acc.z, v.z); acc.w = fmaxf(acc.w, v.w);
            }
        }
    }
    float4 b = f4[node * 32 + lane];
    float4 h;
    if (c == 0) h = b;
    else { h.x = b.x + acc.x; h.y = b.y + acc.y;
           h.z = b.z + acc.z; h.w = b.w + acc.w; }
    reinterpret_cast<float4*>(d_H)[node * 32 + lane] = h;
}

// ------------------ prep: split W -> bf16 hi/lo, [n][k] swizzled -----------
__global__ void prep_kernel(const float* __restrict__ W1,
                            const float* __restrict__ W2) {
    int idx = blockIdx.x * blockDim.x + threadIdx.x;   // 0..32767
    if (idx >= 2 * D * D) return;
    int which = idx >> 14;
    int e = idx & (D * D - 1);
    int k = e >> 7, n = e & 127;                       // consecutive n: coalesced
    const float* W = which ? W2 : W1;
    float x = W[k * D + n];                            // W[k][n]
    __nv_bfloat16 h = __float2bfloat16(x);
    __nv_bfloat16 l = __float2bfloat16(x - __bfloat162float(h));
    int off = swz(n, k * 2) >> 1;                      // B image: row=n, col=k
    if (which) { d_W2hi[off] = h; d_W2lo[off] = l; }
    else       { d_W1hi[off] = h; d_W1lo[off] = l; }
}

// -------------- mma.sync bf16-split GEMM + fused BN column stats -----------
// 512 threads = 16 warps (4m x 4n). Warp tile m32 x n32. Full K=128 in smem.
#define SM_AHI 0
#define SM_ALO 32768
#define SM_BHI 65536
#define SM_BLO 98304
#define GEMM_SMEM 131072
#define SM_YT   0              // epilogue reuse (A + start of BHI dead)
#define SM_PS   98304          // stat partials (BLO dead)
#define YT_PITCH 132

__global__ void __launch_bounds__(512)
gemm_kernel(const float* __restrict__ A,
            const __nv_bfloat16* __restrict__ Whi,
            const __nv_bfloat16* __restrict__ Wlo,
            const float* __restrict__ bias, float* __restrict__ Y,
            const float* __restrict__ ts, const float* __restrict__ tt) {
    extern __shared__ char smem[];
    const int tid  = threadIdx.x;
    const int wid  = tid >> 5;
    const int lane = tid & 31;
    const int block_row = blockIdx.x * 128;
    const unsigned smem_b = smem_u32(smem);

    const int warp_m = (wid & 3) * 32;     // 0,32,64,96
    const int warp_n = (wid >> 2) * 32;    // 0,32,64,96

    // ---- W images via cp.async (overlaps with A convert below) ----
    {
        const char* sh = reinterpret_cast<const char*>(Whi);
        const char* sl = reinterpret_cast<const char*>(Wlo);
        #pragma unroll
        for (int i = 0; i < 4; ++i) {
            int off = (tid + i * 512) * 16;            // 0..32767
            CP_ASYNC16(smem_b + SM_BHI + off, sh + off);
            CP_ASYNC16(smem_b + SM_BLO + off, sl + off);
        }
    }

    // ---- A tile: fp32 -> bf16 hi/lo, swizzled row-major [m][k] ----
    const float4* A4 = reinterpret_cast<const float4*>(A);
    #pragma unroll
    for (int i = 0; i < 8; ++i) {
        int f4i = tid + i * 512;             // 0..4095
        int m   = f4i >> 5;
        int k4  = f4i & 31;
        int row = block_row + m;
        float4 v = make_float4(0.f, 0.f, 0.f, 0.f);
        if (row < N_NODES) v = A4[row * 32 + k4];
        if (ts) {
            int k = k4 * 4;
            v.x = fmaxf(fmaf(ts[k+0], v.x, tt[k+0]), 0.f);
            v.y = fmaxf(fmaf(ts[k+1], v.y, tt[k+1]), 0.f);
            v.z = fmaxf(fmaf(ts[k+2], v.z, tt[k+2]), 0.f);
            v.w = fmaxf(fmaf(ts[k+3], v.w, tt[k+3]), 0.f);
        }
        __nv_bfloat162 h01 = __floats2bfloat162_rn(v.x, v.y);
        __nv_bfloat162 h23 = __floats2bfloat162_rn(v.z, v.w);
        float2 hf01 = __bfloat1622float2(h01);
        float2 hf23 = __bfloat1622float2(h23);
        __nv_bfloat162 l01 = __floats2bfloat162_rn(v.x - hf01.x, v.y - hf01.y);
        __nv_bfloat162 l23 = __floats2bfloat162_rn(v.z - hf23.x, v.w - hf23.y);
        int off = swz(m, k4 * 8);            // 8B chunk, 8-aligned, swizzle-safe
        ull hp = ((ull)*(unsigned*)&h23 << 32) | *(unsigned*)&h01;
        ull lp = ((ull)*(unsigned*)&l23 << 32) | *(unsigned*)&l01;
        *reinterpret_cast<ull*>(smem + SM_AHI + off) = hp;
        *reinterpret_cast<ull*>(smem + SM_ALO + off) = lp;
    }
    CP_ASYNC_WAIT_ALL();
    __syncthreads();

    // ---- mainloop: 8 K-steps of 16; 3 split terms, fp32 accum ----
    float c[2][4][4];
    #pragma unroll
    for (int mt = 0; mt < 2; ++mt)
        #pragma unroll
        for (int nt = 0; nt < 4; ++nt)
            #pragma unroll
            for (int q = 0; q < 4; ++q) c[mt][nt][q] = 0.f;

    const int a_row  = lane & 15;
    const int a_koff = (lane >> 4) * 8;
    const int b_nrow = (lane & 7) + ((lane >> 4) & 1) * 8;
    const int b_koff = ((lane >> 3) & 1) * 8;

    #pragma unroll
    for (int ks = 0; ks < 8; ++ks) {
        int kb = ks * 16;
        unsigned bh[8], bl[8];
        #pragma unroll
        for (int p = 0; p < 2; ++p) {
            int n = warp_n + p * 16 + b_nrow;
            int boff = swz(n, (kb + b_koff) * 2);
            LDSM_X4(bh[p*4+0], bh[p*4+1], bh[p*4+2], bh[p*4+3],
                    smem_b + SM_BHI + boff);
            LDSM_X4(bl[p*4+0], bl[p*4+1], bl[p*4+2], bl[p*4+3],
                    smem_b + SM_BLO + boff);
        }
        #pragma unroll
        for (int mt = 0; mt < 2; ++mt) {
            int m = warp_m + mt * 16 + a_row;
            int aoff = swz(m, (kb + a_koff) * 2);
            unsigned ah0, ah1, ah2, ah3, al0, al1, al2, al3;
            LDSM_X4(ah0, ah1, ah2, ah3, smem_b + SM_AHI + aoff);
            LDSM_X4(al0, al1, al2, al3, smem_b + SM_ALO + aoff);
            #pragma unroll
            for (int nt = 0; nt < 4; ++nt) {
                unsigned b0h = bh[(nt >> 1) * 4 + (nt & 1) * 2];
                unsigned b1h = bh[(nt >> 1) * 4 + (nt & 1) * 2 + 1];
                unsigned b0l = bl[(nt >> 1) * 4 + (nt & 1) * 2];
                unsigned b1l = bl[(nt >> 1) * 4 + (nt & 1) * 2 + 1];
                MMA_BF16(c[mt][nt][0], c[mt][nt][1], c[mt][nt][2], c[mt][nt][3],
                         ah0, ah1, ah2, ah3, b0h, b1h);
                MMA_BF16(c[mt][nt][0], c[mt][nt][1], c[mt][nt][2], c[mt][nt][3],
                         ah0, ah1, ah2, ah3, b0l, b1l);
                MMA_BF16(c[mt][nt][0], c[mt][nt][1], c[mt][nt][2], c[mt][nt][3],
                         al0, al1, al2, al3, b0h, b1h);
            }
        }
    }
    __syncthreads();   // A smem dead; reuse as Yt

    // ---- epilogue: fragments (+bias, zero invalid rows) -> smem Yt ----
    float* Yt = reinterpret_cast<float*>(smem + SM_YT);   // [128][YT_PITCH]
    {
        int fr = lane >> 2;                  // 0..7
        int fc = (lane & 3) * 2;
        #pragma unroll
        for (int mt = 0; mt < 2; ++mt) {
            int r0 = warp_m + mt * 16 + fr;
            bool v0 = (block_row + r0)     < N_NODES;
            bool v1 = (block_row + r0 + 8) < N_NODES;
            #pragma unroll
            for (int nt = 0; nt < 4; ++nt) {
                int cc = warp_n + nt * 8 + fc;
                float bb0 = bias[cc], bb1 = bias[cc + 1];
                Yt[r0 * YT_PITCH + cc]           = v0 ? c[mt][nt][0] + bb0 : 0.f;
                Yt[r0 * YT_PITCH + cc + 1]       = v0 ? c[mt][nt][1] + bb1 : 0.f;
                Yt[(r0 + 8) * YT_PITCH + cc]     = v1 ? c[mt][nt][2] + bb0 : 0.f;
                Yt[(r0 + 8) * YT_PITCH + cc + 1] = v1 ? c[mt][nt][3] + bb1 : 0.f;
            }
        }
    }
    __syncthreads();

    // ---- gmem write + deterministic column stats from Yt ----
    {
        float* psm = reinterpret_cast<float*>(smem + SM_PS);          // [16][128]
        float* psq = reinterpret_cast<float*>(smem + SM_PS + 8192);   // [16][128]
        int c4   = tid & 31;                 // cols c4*4 .. +3
        int rseg = tid >> 5;                 // rows rseg*8 .. +7
        float cs[4] = {0.f, 0.f, 0.f, 0.f};
        float cq[4] = {0.f, 0.f, 0.f, 0.f};
        #pragma unroll
        for (int r = 0; r < 8; ++r) {
            int row = rseg * 8 + r;
            float4 v = *reinterpret_cast<float4*>(&Yt[row * YT_PITCH + c4 * 4]);
            cs[0] += v.x; cq[0] += v.x * v.x;
            cs[1] += v.y; cq[1] += v.y * v.y;
            cs[2] += v.z; cq[2] += v.z * v.z;
            cs[3] += v.w; cq[3] += v.w * v.w;
            int grow = block_row + row;
            if (grow < N_NODES)
                *reinterpret_cast<float4*>(Y + grow * 128 + c4 * 4) = v;
        }
        #pragma unroll
        for (int j = 0; j < 4; ++j) {
            psm[rseg * 128 + c4 * 4 + j] = cs[j];
            psq[rseg * 128 + c4 * 4 + j] = cq[j];
        }
        __syncthreads();
        if (tid < 128) {
            float S = 0.f, Q = 0.f;
            #pragma unroll
            for (int t = 0; t < 16; ++t) {   // fixed order -> deterministic
                S += psm[t * 128 + tid];
                Q += psq[t * 128 + tid];
            }
            d_psum[blockIdx.x * 128 + tid] = S;
            d_psq [blockIdx.x * 128 + tid] = Q;
        }
    }
}

// ----------------------------- colreduce (phase-3 stats) -------------------
__global__ void colreduce_kernel(const float* __restrict__ X,
                                 const float* __restrict__ ts,
                                 const float* __restrict__ tt) {
    int c = threadIdx.x;
    int r0 = blockIdx.x * 100;
    int r1 = r0 + 100; if (r1 > N_NODES) r1 = N_NODES;
    float sc = ts[c], sh = tt[c];
    float sm = 0.f, sq = 0.f;
    for (int r = r0; r < r1; ++r) {
        float v = fmaxf(fmaf(sc, X[r * 128 + c], sh), 0.f);
        sm += v; sq += v * v;
    }
    d_psum[blockIdx.x * 128 + c] = sm;
    d_psq [blockIdx.x * 128 + c] = sq;
}

// ----------------------------- parallel finalize (R9, proven) --------------
__global__ void __launch_bounds__(256)
finalize_kernel(const float* __restrict__ g, const float* __restrict__ be,
                float* __restrict__ scale, float* __restrict__ shift,
                int nblk) {
    __shared__ float ss[256];
    __shared__ float sq[256];
    const int c = blockIdx.x;
    const int t = threadIdx.x;
    float sm = 0.f, q = 0.f;
    for (int b = t; b < nblk; b += 256) {
        sm += d_psum[b * 128 + c];
        q  += d_psq [b * 128 + c];
    }
    ss[t] = sm; sq[t] = q;
    __syncthreads();
    #pragma unroll
    for (int s = 128; s > 0; s >>= 1) {
        if (t < s) { ss[t] += ss[t + s]; sq[t] += sq[t + s]; }
        __syncthreads();
    }
    if (t == 0) {
        float m = ss[0] / (float)N_NODES;
        float v = sq[0] / (float)N_NODES - m * m;
        float a = g[c] * rsqrtf(v + BN_EPS);
        scale[c] = a;
        shift[c] = be[c] - m * a;
    }
}

// ----------------------------- final elementwise (float4) ------------------
__global__ void final_kernel(float4* __restrict__ out4) {
    int i = blockIdx.x * blockDim.x + threadIdx.x;
    if (i >= N_NODES * 32) return;
    if (i < N_NODES) d_cnt[i] = 0;               // prep next graph replay
    int c = (i & 31) * 4;
    float4 v = reinterpret_cast<const float4*>(d_Y2)[i];
    float4 o;
    o.x = fmaf(d_scale3[c+0], fmaxf(fmaf(d_scale2[c+0], v.x, d_shift2[c+0]), 0.f), d_shift3[c+0]);
    o.y = fmaf(d_scale3[c+1], fmaxf(fmaf(d_scale2[c+1], v.y, d_shift2[c+1]), 0.f), d_shift3[c+1]);
    o.z = fmaf(d_scale3[c+2], fmaxf(fmaf(d_scale2[c+2], v.z, d_shift2[c+2]), 0.f), d_shift3[c+2]);
    o.w = fmaf(d_scale3[c+3], fmaxf(fmaf(d_scale2[c+3], v.w, d_shift2[c+3]), 0.f), d_shift3[c+3]);
    out4[i] = o;
}

// ---------------------------------------------------------------------------
extern "C" void kernel_launch(void* const* d_in, const int* in_sizes, int n_in,
                              void* d_out, int out_size) {
    const float* feats = (const float*)d_in[0];
    const int*   src   = (const int*)  d_in[1];
    const int*   dst   = (const int*)  d_in[2];
    const float* W1    = (const float*)d_in[3];
    const float* b1    = (const float*)d_in[4];
    const float* g1    = (const float*)d_in[5];
    const float* be1   = (const float*)d_in[6];
    const float* W2    = (const float*)d_in[7];
    const float* b2    = (const float*)d_in[8];
    const float* g2    = (const float*)d_in[9];
    const float* be2   = (const float*)d_in[10];
    const float* g3    = (const float*)d_in[11];
    const float* be3   = (const float*)d_in[12];
    float* out = (float*)d_out;

    static bool attr_set = false;
    if (!attr_set) {
        cudaFuncSetAttribute(gemm_kernel,
                             cudaFuncAttributeMaxDynamicSharedMemorySize,
                             GEMM_SMEM);
        attr_set = true;
    }

    float *s1, *t1, *s2, *t2, *s3, *t3;
    cudaGetSymbolAddress((void**)&s1, d_scale1);
    cudaGetSymbolAddress((void**)&t1, d_shift1);
    cudaGetSymbolAddress((void**)&s2, d_scale2);
    cudaGetSymbolAddress((void**)&t2, d_shift2);
    cudaGetSymbolAddress((void**)&s3, d_scale3);
    cudaGetSymbolAddress((void**)&t3, d_shift3);
    float *H, *Y1, *Y2;
    cudaGetSymbolAddress((void**)&H,  d_H);
    cudaGetSymbolAddress((void**)&Y1, d_Y1);
    cudaGetSymbolAddress((void**)&Y2, d_Y2);
    __nv_bfloat16 *w1h, *w1l, *w2h, *w2l;
    cudaGetSymbolAddress((void**)&w1h, d_W1hi);
    cudaGetSymbolAddress((void**)&w1l, d_W1lo);
    cudaGetSymbolAddress((void**)&w2h, d_W2hi);
    cudaGetSymbolAddress((void**)&w2l, d_W2lo);

    prep_kernel<<<128, 256>>>(W1, W2);
    scatter_kernel<<<(N_EDGES + 255) / 256, 256>>>(src, dst);
    aggregate_kernel<<<(N_NODES * 32 + 255) / 256, 256>>>(feats, src, dst);

    // Y1 = H @ W1 + b1   (+ fused column stats)
    gemm_kernel<<<NBLK_GEMM, 512, GEMM_SMEM>>>(H, w1h, w1l, b1, Y1,
                                               nullptr, nullptr);
    finalize_kernel<<<D, 256>>>(g1, be1, s1, t1, NBLK_GEMM);
    // Y2 = relu(BN(Y1)) @ W2 + b2   (BN+ReLU fused into A load)
    gemm_kernel<<<NBLK_GEMM, 512, GEMM_SMEM>>>(Y1, w2h, w2l, b2, Y2,
                                               s1, t1);
    finalize_kernel<<<D, 256>>>(g2, be2, s2, t2, NBLK_GEMM);
    // stats of h2 = relu(BN(Y2))
    colreduce_kernel<<<NBLK_RED, 128>>>(Y2, s2, t2);
    finalize_kernel<<<D, 256>>>(g3, be3, s3, t3, NBLK_RED);
    // out = BN3(relu(BN2(Y2)))  (+ re-zero d_cnt)
    final_kernel<<<(N_NODES * 32 + 255) / 256, 256>>>(
        reinterpret_cast<float4*>(out));
}